// round 14
// baseline (speedup 1.0000x reference)
#include <cuda_runtime.h>
#include <cuda_bf16.h>
#include <cuda_fp16.h>
#include <math.h>
#include <stdint.h>

// ---------------- problem constants ----------------
#define Bb    2
#define Ss    2048
#define MTOK  4096
#define NBATCH 16
#define SCALE 0.08838834764831845f   // 1/sqrt(128)

// ---------------- scratch (device globals; no allocation) ----------------
__device__ float g_cq[MTOK * 128];
__device__ float g_q[MTOK * 1024];
__device__ float g_ckvkr[MTOK * 192];
__device__ float g_ckv[MTOK * 128];
__device__ float g_kr[MTOK * 64];
__device__ float g_kv[MTOK * 2560];
// fp16 attention operands
__device__ __half g_q16[NBATCH * Ss * 128];
__device__ __half g_k16[NBATCH * Ss * 128];
__device__ __half g_v16[NBATCH * 256 * Ss];            // V^T per (b,h)
__device__ __half g_s16[(long long)NBATCH * Ss * Ss];  // 134 MB scores
__device__ __half g_p16[(long long)NBATCH * Ss * Ss];  // 134 MB probs
__device__ __half g_attn16[MTOK * 2048];
__device__ __half g_wo16[1024 * 2048];                 // w_o^T fp16
// pre-split bf16 B operands (hi/lo) for 3-pass projections
__device__ __nv_bfloat16 g_wdq_h[128 * 1024],  g_wdq_l[128 * 1024];
__device__ __nv_bfloat16 g_wuq_h[1024 * 128],  g_wuq_l[1024 * 128];
__device__ __nv_bfloat16 g_wdkv_h[192 * 1024], g_wdkv_l[192 * 1024];
__device__ __nv_bfloat16 g_wukuv_h[2560 * 128], g_wukuv_l[2560 * 128];

// ================= helpers =================
__device__ __forceinline__ uint32_t smem_u32(const void* p) {
    uint32_t a;
    asm("{ .reg .u64 t; cvta.to.shared.u64 t, %1; cvt.u32.u64 %0, t; }" : "=r"(a) : "l"(p));
    return a;
}

#define LDSM4(r0, r1, r2, r3, addr) \
    asm volatile("ldmatrix.sync.aligned.m8n8.x4.shared.b16 {%0,%1,%2,%3}, [%4];" \
                 : "=r"(r0), "=r"(r1), "=r"(r2), "=r"(r3) : "r"(addr))

#define MMA_BF16(d, a, b) \
    asm volatile("mma.sync.aligned.m16n8k16.row.col.f32.bf16.bf16.f32 " \
                 "{%0,%1,%2,%3}, {%4,%5,%6,%7}, {%8,%9}, {%0,%1,%2,%3};" \
                 : "+f"((d)[0]), "+f"((d)[1]), "+f"((d)[2]), "+f"((d)[3]) \
                 : "r"((a)[0]), "r"((a)[1]), "r"((a)[2]), "r"((a)[3]), \
                   "r"((b)[0]), "r"((b)[1]))

#define MMA_FP16(d, a, b) \
    asm volatile("mma.sync.aligned.m16n8k16.row.col.f32.f16.f16.f32 " \
                 "{%0,%1,%2,%3}, {%4,%5,%6,%7}, {%8,%9}, {%0,%1,%2,%3};" \
                 : "+f"((d)[0]), "+f"((d)[1]), "+f"((d)[2]), "+f"((d)[3]) \
                 : "r"((a)[0]), "r"((a)[1]), "r"((a)[2]), "r"((a)[3]), \
                   "r"((b)[0]), "r"((b)[1]))

__device__ __forceinline__ void split2(float x, float y, uint32_t& hi, uint32_t& lo) {
    __nv_bfloat16 hx = __float2bfloat16(x), hy = __float2bfloat16(y);
    __nv_bfloat16 lx = __float2bfloat16(x - __bfloat162float(hx));
    __nv_bfloat16 ly = __float2bfloat16(y - __bfloat162float(hy));
    __nv_bfloat162 h = __halves2bfloat162(hx, hy);
    __nv_bfloat162 l = __halves2bfloat162(lx, ly);
    hi = *reinterpret_cast<uint32_t*>(&h);
    lo = *reinterpret_cast<uint32_t*>(&l);
}
__device__ __forceinline__ void cpa16(uint32_t dst, const void* src) {
    asm volatile("cp.async.cg.shared.global [%0], [%1], 16;" :: "r"(dst), "l"(src));
}
#define CP_COMMIT() asm volatile("cp.async.commit_group;" ::: "memory")
#define CP_WAIT0()  asm volatile("cp.async.wait_group 0;" ::: "memory")

// ================= double-buffered split-bf16 GEMM (R9/R12 verbatim) ====
#define SROW 40
#define TILE_B ((uint32_t)(128 * SROW * 2))
#define STAGE_B (4 * TILE_B)
#define GEMM_SMEM (2 * STAGE_B)               // 81920

__global__ void __launch_bounds__(256)
hgemm2_kernel(const float* __restrict__ A, int lda, long long sA,
              const __nv_bfloat16* __restrict__ Bh,
              const __nv_bfloat16* __restrict__ Bl, int ldb, long long sB,
              const float* __restrict__ bias,
              float* __restrict__ C, int ldc, long long sC,
              int N, int K, float alpha)
{
    extern __shared__ char smraw[];
    const uint32_t sb = smem_u32(smraw);

    const int tid  = threadIdx.x;
    const int lane = tid & 31;
    const int wid  = tid >> 5;
    const int wm   = wid & 1;
    const int wn   = wid >> 1;

    const int z  = blockIdx.z;
    A  += z * sA;
    Bh += z * sB;
    Bl += z * sB;
    const int m0 = blockIdx.y * 128;
    const int n0 = blockIdx.x * 128;

    const int lr  = tid >> 2;
    const int lc4 = (tid & 3) * 2;
    float4 pa[4];

    float acc[4][4][4];
#pragma unroll
    for (int i = 0; i < 4; i++)
#pragma unroll
        for (int j = 0; j < 4; j++)
#pragma unroll
            for (int c = 0; c < 4; c++) acc[i][j][c] = 0.f;

#define BUF_AH(t) (sb + (t) * STAGE_B)
#define BUF_AL(t) (sb + (t) * STAGE_B + TILE_B)
#define BUF_BH(t) (sb + (t) * STAGE_B + 2 * TILE_B)
#define BUF_BL(t) (sb + (t) * STAGE_B + 3 * TILE_B)

#define PREFETCH_A(kt)                                                          \
    {                                                                           \
        _Pragma("unroll")                                                       \
        for (int u = 0; u < 4; u++) {                                           \
            int r  = lr + (u >> 1) * 64;                                        \
            int c4 = lc4 + (u & 1);                                             \
            pa[u] = *reinterpret_cast<const float4*>(                           \
                A + (long long)(m0 + r) * lda + (kt) + c4 * 4);                 \
        }                                                                       \
    }

#define STORE_A(t)                                                              \
    {                                                                           \
        _Pragma("unroll")                                                       \
        for (int u = 0; u < 4; u++) {                                           \
            int r = lr + (u >> 1) * 64;                                         \
            int c = (lc4 + (u & 1)) * 4;                                        \
            uint32_t h0, l0, h1, l1;                                            \
            split2(pa[u].x, pa[u].y, h0, l0);                                   \
            split2(pa[u].z, pa[u].w, h1, l1);                                   \
            uint32_t off = (uint32_t)(r * SROW + c) * 2;                        \
            asm volatile("st.shared.v2.b32 [%0], {%1,%2};" ::                   \
                         "r"(BUF_AH(t) + off), "r"(h0), "r"(h1) : "memory");    \
            asm volatile("st.shared.v2.b32 [%0], {%1,%2};" ::                   \
                         "r"(BUF_AL(t) + off), "r"(l0), "r"(l1) : "memory");    \
        }                                                                       \
    }

#define LOAD_B(kt, t)                                                           \
    {                                                                           \
        _Pragma("unroll")                                                       \
        for (int u = 0; u < 2; u++) {                                           \
            int id = tid * 2 + u;                                               \
            int r  = id >> 2;                                                   \
            int cc = (id & 3) * 8;                                              \
            uint32_t doff = (uint32_t)(r * SROW + cc) * 2;                      \
            int gn = n0 + r;                                                    \
            if (gn < N) {                                                       \
                cpa16(BUF_BH(t) + doff, Bh + (long long)gn * ldb + (kt) + cc);  \
                cpa16(BUF_BL(t) + doff, Bl + (long long)gn * ldb + (kt) + cc);  \
            } else {                                                            \
                asm volatile("st.shared.v4.b32 [%0], {%1,%1,%1,%1};" ::         \
                             "r"(BUF_BH(t) + doff), "r"(0) : "memory");         \
                asm volatile("st.shared.v4.b32 [%0], {%1,%1,%1,%1};" ::         \
                             "r"(BUF_BL(t) + doff), "r"(0) : "memory");         \
            }                                                                   \
        }                                                                       \
    }

    PREFETCH_A(0);
    LOAD_B(0, 0);
    CP_COMMIT();
    STORE_A(0);
    CP_WAIT0();
    __syncthreads();

    const int nk = K >> 5;
    for (int s = 0; s < nk; s++) {
        const int cur = s & 1, nxt = cur ^ 1;
        if (s + 1 < nk) {
            PREFETCH_A((s + 1) << 5);
            LOAD_B((s + 1) << 5, nxt);
            CP_COMMIT();
        }

        const uint32_t uAh = BUF_AH(cur), uAl = BUF_AL(cur);
        const uint32_t uBh = BUF_BH(cur), uBl = BUF_BL(cur);
#pragma unroll
        for (int ks = 0; ks < 2; ks++) {
            uint32_t bh[4][2], bl[4][2];
#pragma unroll
            for (int jp = 0; jp < 2; jp++) {
                int rowb = wn * 32 + jp * 16 + (lane & 7) + ((lane & 16) >> 1);
                int kc   = ks * 16 + (lane & 8);
                uint32_t off = (uint32_t)(rowb * SROW + kc) * 2;
                LDSM4(bh[jp * 2][0], bh[jp * 2][1], bh[jp * 2 + 1][0], bh[jp * 2 + 1][1],
                      uBh + off);
                LDSM4(bl[jp * 2][0], bl[jp * 2][1], bl[jp * 2 + 1][0], bl[jp * 2 + 1][1],
                      uBl + off);
            }
#pragma unroll
            for (int i = 0; i < 4; i++) {
                int rowa = wm * 64 + i * 16 + (lane & 7) + (lane & 8);
                int kc   = ks * 16 + ((lane & 16) >> 1);
                uint32_t off = (uint32_t)(rowa * SROW + kc) * 2;
                uint32_t ah[4], al[4];
                LDSM4(ah[0], ah[1], ah[2], ah[3], uAh + off);
                LDSM4(al[0], al[1], al[2], al[3], uAl + off);
#pragma unroll
                for (int j = 0; j < 4; j++) {
                    MMA_BF16(acc[i][j], ah, bh[j]);
                    MMA_BF16(acc[i][j], ah, bl[j]);
                    MMA_BF16(acc[i][j], al, bh[j]);
                }
            }
        }

        if (s + 1 < nk) {
            STORE_A(nxt);
            CP_WAIT0();
        }
        __syncthreads();
    }

    float* Cp = C + z * sC;
#pragma unroll
    for (int j = 0; j < 4; j++) {
        int col = n0 + wn * 32 + j * 8 + (lane & 3) * 2;
        if (col >= N) continue;
        float b0 = 0.f, b1 = 0.f;
        if (bias) { b0 = bias[col]; b1 = bias[col + 1]; }
#pragma unroll
        for (int i = 0; i < 4; i++) {
            int row = m0 + wm * 64 + i * 16 + (lane >> 2);
            float2 v0 = make_float2(acc[i][j][0] * alpha + b0,
                                    acc[i][j][1] * alpha + b1);
            float2 v1 = make_float2(acc[i][j][2] * alpha + b0,
                                    acc[i][j][3] * alpha + b1);
            *reinterpret_cast<float2*>(Cp + (long long)row * ldc + col)       = v0;
            *reinterpret_cast<float2*>(Cp + (long long)(row + 8) * ldc + col) = v1;
        }
    }
#undef BUF_AH
#undef BUF_AL
#undef BUF_BH
#undef BUF_BL
#undef PREFETCH_A
#undef STORE_A
#undef LOAD_B
}

// ================= single-pass fp16 GEMM (R12-validated mainloop) ========
// MODE 0: fp32 out + bias (o-proj)
// MODE 1: fp16 out, alpha applied (QK scores)
// MODE 2: fp16 out permuted [b*Ss+m][h*256+n], z = b*8+h (PV)
// All dims multiples of 128.
#define TILE16 ((uint32_t)(128 * SROW * 2))
#define STAGE16 (2 * TILE16)
#define PV_SMEM (2 * STAGE16)                 // 40960

template <int MODE>
__global__ void __launch_bounds__(256)
hgemm16_kernel(const __half* __restrict__ Ap, int lda, long long sA,
               const __half* __restrict__ Bp, int ldb, long long sB,
               const float* __restrict__ bias,
               float* __restrict__ Cf, __half* __restrict__ Ch,
               int ldc, long long sC, int N, int K, float alpha)
{
    extern __shared__ char smraw[];
    const uint32_t sb = smem_u32(smraw);

    const int tid  = threadIdx.x;
    const int lane = tid & 31;
    const int wid  = tid >> 5;
    const int wm   = wid & 1;
    const int wn   = wid >> 1;

    const int z  = blockIdx.z;
    Ap += z * sA;
    Bp += z * sB;
    const int m0 = blockIdx.y * 128;
    const int n0 = blockIdx.x * 128;

    float acc[4][4][4];
#pragma unroll
    for (int i = 0; i < 4; i++)
#pragma unroll
        for (int j = 0; j < 4; j++)
#pragma unroll
            for (int c = 0; c < 4; c++) acc[i][j][c] = 0.f;

#define BUF16_A(t) (sb + (t) * STAGE16)
#define BUF16_B(t) (sb + (t) * STAGE16 + TILE16)

#define LOAD16(kt, t)                                                           \
    {                                                                           \
        _Pragma("unroll")                                                       \
        for (int u = 0; u < 2; u++) {                                           \
            int id = tid * 2 + u;                                               \
            int r  = id >> 2;                                                   \
            int cc = (id & 3) * 8;                                              \
            uint32_t doff = (uint32_t)(r * SROW + cc) * 2;                      \
            cpa16(BUF16_A(t) + doff, Ap + (long long)(m0 + r) * lda + (kt) + cc); \
            cpa16(BUF16_B(t) + doff, Bp + (long long)(n0 + r) * ldb + (kt) + cc); \
        }                                                                       \
    }

    LOAD16(0, 0);
    CP_COMMIT();
    CP_WAIT0();
    __syncthreads();

    const int nk = K >> 5;
    for (int s = 0; s < nk; s++) {
        const int cur = s & 1, nxt = cur ^ 1;
        if (s + 1 < nk) {
            LOAD16((s + 1) << 5, nxt);
            CP_COMMIT();
        }

        const uint32_t uA = BUF16_A(cur), uB = BUF16_B(cur);
#pragma unroll
        for (int ks = 0; ks < 2; ks++) {
            uint32_t bf[4][2];
#pragma unroll
            for (int jp = 0; jp < 2; jp++) {
                int rowb = wn * 32 + jp * 16 + (lane & 7) + ((lane & 16) >> 1);
                int kc   = ks * 16 + (lane & 8);
                uint32_t off = (uint32_t)(rowb * SROW + kc) * 2;
                LDSM4(bf[jp * 2][0], bf[jp * 2][1], bf[jp * 2 + 1][0], bf[jp * 2 + 1][1],
                      uB + off);
            }
#pragma unroll
            for (int i = 0; i < 4; i++) {
                int rowa = wm * 64 + i * 16 + (lane & 7) + (lane & 8);
                int kc   = ks * 16 + ((lane & 16) >> 1);
                uint32_t off = (uint32_t)(rowa * SROW + kc) * 2;
                uint32_t af[4];
                LDSM4(af[0], af[1], af[2], af[3], uA + off);
#pragma unroll
                for (int j = 0; j < 4; j++)
                    MMA_FP16(acc[i][j], af, bf[j]);
            }
        }

        if (s + 1 < nk) CP_WAIT0();
        __syncthreads();
    }

    if (MODE == 0) {
        float* Cp = Cf + z * sC;
#pragma unroll
        for (int j = 0; j < 4; j++) {
            int col = n0 + wn * 32 + j * 8 + (lane & 3) * 2;
            float b0 = 0.f, b1 = 0.f;
            if (bias) { b0 = bias[col]; b1 = bias[col + 1]; }
#pragma unroll
            for (int i = 0; i < 4; i++) {
                int row = m0 + wm * 64 + i * 16 + (lane >> 2);
                float2 v0 = make_float2(acc[i][j][0] * alpha + b0,
                                        acc[i][j][1] * alpha + b1);
                float2 v1 = make_float2(acc[i][j][2] * alpha + b0,
                                        acc[i][j][3] * alpha + b1);
                *reinterpret_cast<float2*>(Cp + (long long)row * ldc + col)       = v0;
                *reinterpret_cast<float2*>(Cp + (long long)(row + 8) * ldc + col) = v1;
            }
        }
    } else {
        __half* Cp;
        int ldcc;
        if (MODE == 1) {
            Cp = Ch + z * sC;
            ldcc = ldc;
        } else {
            Cp = Ch + ((long long)(z >> 3) * Ss) * 2048 + (z & 7) * 256;
            ldcc = 2048;
        }
#pragma unroll
        for (int j = 0; j < 4; j++) {
            int col = n0 + wn * 32 + j * 8 + (lane & 3) * 2;
#pragma unroll
            for (int i = 0; i < 4; i++) {
                int row = m0 + wm * 64 + i * 16 + (lane >> 2);
                __half2 v0 = __floats2half2_rn(acc[i][j][0] * alpha,
                                               acc[i][j][1] * alpha);
                __half2 v1 = __floats2half2_rn(acc[i][j][2] * alpha,
                                               acc[i][j][3] * alpha);
                *reinterpret_cast<__half2*>(Cp + (long long)row * ldcc + col)       = v0;
                *reinterpret_cast<__half2*>(Cp + (long long)(row + 8) * ldcc + col) = v1;
            }
        }
    }
#undef BUF16_A
#undef BUF16_B
#undef LOAD16
}

// ================= transpose kernels =================
__global__ void transpose_split_kernel(const float* __restrict__ src, int R, int Cc,
                                       __nv_bfloat16* __restrict__ dh,
                                       __nv_bfloat16* __restrict__ dl)
{
    __shared__ float t[32][33];
    int r0 = blockIdx.y * 32, c0 = blockIdx.x * 32;
    int tx = threadIdx.x, ty = threadIdx.y;    // 32 x 8
#pragma unroll
    for (int i = 0; i < 32; i += 8)
        if (r0 + ty + i < R && c0 + tx < Cc)
            t[ty + i][tx] = src[(long long)(r0 + ty + i) * Cc + c0 + tx];
    __syncthreads();
#pragma unroll
    for (int i = 0; i < 32; i += 8)
        if (c0 + ty + i < Cc && r0 + tx < R) {
            float v = t[tx][ty + i];
            __nv_bfloat16 h = __float2bfloat16(v);
            long long o = (long long)(c0 + ty + i) * R + r0 + tx;
            dh[o] = h;
            dl[o] = __float2bfloat16(v - __bfloat162float(h));
        }
}

__global__ void transpose_half_kernel(const float* __restrict__ src, int R, int Cc,
                                      __half* __restrict__ dst)
{
    __shared__ float t[32][33];
    int r0 = blockIdx.y * 32, c0 = blockIdx.x * 32;
    int tx = threadIdx.x, ty = threadIdx.y;
#pragma unroll
    for (int i = 0; i < 32; i += 8)
        if (r0 + ty + i < R && c0 + tx < Cc)
            t[ty + i][tx] = src[(long long)(r0 + ty + i) * Cc + c0 + tx];
    __syncthreads();
#pragma unroll
    for (int i = 0; i < 32; i += 8)
        if (c0 + ty + i < Cc && r0 + tx < R)
            dst[(long long)(c0 + ty + i) * R + r0 + tx] = __float2half_rn(t[tx][ty + i]);
}

// V^T fp16
__global__ void build_vT_half_kernel(const float* __restrict__ kv,
                                     __half* __restrict__ vt)
{
    __shared__ float t[32][33];
    int z = blockIdx.z, b = z >> 3, h = z & 7;
    const float* src = kv + (long long)b * 2048 * 2560 + 512 + h * 256;
    long long dbase = (long long)z * 256 * 2048;
    int s0 = blockIdx.x * 32, d0 = blockIdx.y * 32;
    int tx = threadIdx.x, ty = threadIdx.y;
#pragma unroll
    for (int i = 0; i < 32; i += 8)
        t[ty + i][tx] = src[(long long)(s0 + ty + i) * 2560 + d0 + tx];
    __syncthreads();
#pragma unroll
    for (int i = 0; i < 32; i += 8)
        vt[dbase + (long long)(d0 + ty + i) * 2048 + s0 + tx] =
            __float2half_rn(t[tx][ty + i]);
}

// ================= elementwise kernels =================
__global__ void rmsnorm128_kernel(float* __restrict__ buf, const float* __restrict__ w)
{
    int row = blockIdx.x, tid = threadIdx.x;
    float v = buf[row * 128 + tid];
    float ss = v * v;
#pragma unroll
    for (int o = 16; o; o >>= 1) ss += __shfl_xor_sync(0xffffffffu, ss, o);
    __shared__ float red[4];
    if ((tid & 31) == 0) red[tid >> 5] = ss;
    __syncthreads();
    float tot = red[0] + red[1] + red[2] + red[3];
    float rs = rsqrtf(tot * (1.f / 128.f) + 1e-8f);
    buf[row * 128 + tid] = w[tid] * v * rs;
}

__global__ void post_ckvkr_kernel(const float* __restrict__ in,
                                  const float* __restrict__ w,
                                  const int* __restrict__ pos,
                                  float* __restrict__ ckv,
                                  float* __restrict__ kr)
{
    int row = blockIdx.x, tid = threadIdx.x;
    float v = in[row * 192 + tid];
    float ss = v * v;
#pragma unroll
    for (int o = 16; o; o >>= 1) ss += __shfl_xor_sync(0xffffffffu, ss, o);
    __shared__ float red[4];
    if ((tid & 31) == 0) red[tid >> 5] = ss;
    __syncthreads();
    float tot = red[0] + red[1] + red[2] + red[3];
    float rs = rsqrtf(tot * (1.f / 128.f) + 1e-8f);
    ckv[row * 128 + tid] = w[tid] * v * rs;

    if (tid < 32) {
        float xe = in[row * 192 + 128 + 2 * tid];
        float xo = in[row * 192 + 128 + 2 * tid + 1];
        float invf = powf(10000.f, -(float)(2 * tid) / 64.f);
        float ang = (float)pos[row] * invf;
        float s, c;
        sincosf(ang, &s, &c);
        kr[row * 64 + 2 * tid]     = xe * c - xo * s;
        kr[row * 64 + 2 * tid + 1] = xe * s + xo * c;
    }
}

// build q_states fp16 with rope
__global__ void build_q_half_kernel(const float* __restrict__ q,
                                    const int* __restrict__ pos,
                                    __half* __restrict__ q16)
{
    int idx = blockIdx.x * blockDim.x + threadIdx.x;
    int d = idx & 127;
    int t = idx >> 7;
    int qp = t & (Ss - 1);
    int zz = t >> 11;
    int b = zz >> 3, h = zz & 7;
    int row = b * Ss + qp;
    float val;
    if (d < 96) {
        val = q[row * 1024 + h * 96 + d];
    } else {
        int r = d - 96;
        int i = r >> 1;
        float xe = q[row * 1024 + 768 + h * 32 + 2 * i];
        float xo = q[row * 1024 + 768 + h * 32 + 2 * i + 1];
        float invf = powf(10000.f, -(float)(2 * i) / 32.f);
        float ang = (float)pos[row] * invf;
        float s, c;
        sincosf(ang, &s, &c);
        val = (r & 1) ? (xe * s + xo * c) : (xe * c - xo * s);
    }
    q16[idx] = __float2half_rn(val);
}

// build k_states fp16
__global__ void build_k_half_kernel(const float* __restrict__ kv,
                                    const float* __restrict__ kr,
                                    __half* __restrict__ k16)
{
    int idx = blockIdx.x * blockDim.x + threadIdx.x;
    int d = idx & 127;
    int t = idx >> 7;
    int qp = t & (Ss - 1);
    int zz = t >> 11;
    int b = zz >> 3, h = zz & 7;
    int row = b * Ss + qp;
    float v = (d < 64) ? kv[row * 2560 + h * 64 + d] : kr[row * 64 + (d - 64)];
    k16[idx] = __float2half_rn(v);
}

// row softmax over 2048 cols: fp16 in -> fp16 out. Thread owns 8 contiguous.
__global__ void softmax16_kernel(const __half* __restrict__ s16,
                                 __half* __restrict__ p16)
{
    const __half* p = s16 + (long long)blockIdx.x * 2048;
    __half* o = p16 + (long long)blockIdx.x * 2048;
    int tid = threadIdx.x;
    uint4 raw = *reinterpret_cast<const uint4*>(p + tid * 8);
    __half* hp = reinterpret_cast<__half*>(&raw);
    float v[8];
#pragma unroll
    for (int i = 0; i < 8; i++) v[i] = __half2float(hp[i]);
    float m = v[0];
#pragma unroll
    for (int i = 1; i < 8; i++) m = fmaxf(m, v[i]);
#pragma unroll
    for (int of = 16; of; of >>= 1) m = fmaxf(m, __shfl_xor_sync(0xffffffffu, m, of));
    __shared__ float redm[8];
    int lane = tid & 31, w = tid >> 5;
    if (lane == 0) redm[w] = m;
    __syncthreads();
    m = redm[0];
#pragma unroll
    for (int i = 1; i < 8; i++) m = fmaxf(m, redm[i]);
    float sum = 0.f;
#pragma unroll
    for (int i = 0; i < 8; i++) { v[i] = __expf(v[i] - m); sum += v[i]; }
#pragma unroll
    for (int of = 16; of; of >>= 1) sum += __shfl_xor_sync(0xffffffffu, sum, of);
    __shared__ float reds[8];
    if (lane == 0) reds[w] = sum;
    __syncthreads();
    sum = 0.f;
#pragma unroll
    for (int i = 0; i < 8; i++) sum += reds[i];
    float inv = 1.f / sum;
    __half h[8];
#pragma unroll
    for (int i = 0; i < 8; i++) h[i] = __float2half_rn(v[i] * inv);
    *reinterpret_cast<uint4*>(o + tid * 8) = *reinterpret_cast<uint4*>(h);
}

// ================= launch =================
extern "C" void kernel_launch(void* const* d_in, const int* in_sizes, int n_in,
                              void* d_out, int out_size)
{
    const float* x         = (const float*)d_in[0];
    const int*   pos       = (const int*)  d_in[1];
    const float* w_dq_w    = (const float*)d_in[2];
    const float* w_dq_b    = (const float*)d_in[3];
    const float* q_norm_w  = (const float*)d_in[4];
    const float* w_uq_qr_w = (const float*)d_in[5];
    const float* w_uq_qr_b = (const float*)d_in[6];
    const float* w_dkv_w   = (const float*)d_in[7];
    const float* w_dkv_b   = (const float*)d_in[8];
    const float* kv_norm_w = (const float*)d_in[9];
    const float* w_ukuv_w  = (const float*)d_in[10];
    const float* w_ukuv_b  = (const float*)d_in[11];
    const float* w_o_w     = (const float*)d_in[12];
    const float* w_o_b     = (const float*)d_in[13];
    float* out = (float*)d_out;

    float *p_cq, *p_q, *p_ckvkr, *p_ckv, *p_kr, *p_kv;
    __half *p_q16, *p_k16, *p_v16, *p_s16, *p_p16, *p_attn16, *p_wo16;
    __nv_bfloat16 *p_wdqh, *p_wdql, *p_wuqh, *p_wuql, *p_wdkvh, *p_wdkvl;
    __nv_bfloat16 *p_wukuvh, *p_wukuvl;
    cudaGetSymbolAddress((void**)&p_cq,    g_cq);
    cudaGetSymbolAddress((void**)&p_q,     g_q);
    cudaGetSymbolAddress((void**)&p_ckvkr, g_ckvkr);
    cudaGetSymbolAddress((void**)&p_ckv,   g_ckv);
    cudaGetSymbolAddress((void**)&p_kr,    g_kr);
    cudaGetSymbolAddress((void**)&p_kv,    g_kv);
    cudaGetSymbolAddress((void**)&p_q16,   g_q16);
    cudaGetSymbolAddress((void**)&p_k16,   g_k16);
    cudaGetSymbolAddress((void**)&p_v16,   g_v16);
    cudaGetSymbolAddress((void**)&p_s16,   g_s16);
    cudaGetSymbolAddress((void**)&p_p16,   g_p16);
    cudaGetSymbolAddress((void**)&p_attn16, g_attn16);
    cudaGetSymbolAddress((void**)&p_wo16,  g_wo16);
    cudaGetSymbolAddress((void**)&p_wdqh,  g_wdq_h);
    cudaGetSymbolAddress((void**)&p_wdql,  g_wdq_l);
    cudaGetSymbolAddress((void**)&p_wuqh,  g_wuq_h);
    cudaGetSymbolAddress((void**)&p_wuql,  g_wuq_l);
    cudaGetSymbolAddress((void**)&p_wdkvh, g_wdkv_h);
    cudaGetSymbolAddress((void**)&p_wdkvl, g_wdkv_l);
    cudaGetSymbolAddress((void**)&p_wukuvh, g_wukuv_h);
    cudaGetSymbolAddress((void**)&p_wukuvl, g_wukuv_l);

    cudaFuncSetAttribute(hgemm2_kernel, cudaFuncAttributeMaxDynamicSharedMemorySize,
                         GEMM_SMEM);
    cudaFuncSetAttribute(hgemm16_kernel<0>, cudaFuncAttributeMaxDynamicSharedMemorySize,
                         PV_SMEM);
    cudaFuncSetAttribute(hgemm16_kernel<1>, cudaFuncAttributeMaxDynamicSharedMemorySize,
                         PV_SMEM);
    cudaFuncSetAttribute(hgemm16_kernel<2>, cudaFuncAttributeMaxDynamicSharedMemorySize,
                         PV_SMEM);

    dim3 tb(32, 8);

    // ---- weight transposes ----
    transpose_split_kernel<<<dim3(4, 32),  tb>>>(w_dq_w,    1024, 128,  p_wdqh, p_wdql);
    transpose_split_kernel<<<dim3(32, 4),  tb>>>(w_uq_qr_w, 128, 1024,  p_wuqh, p_wuql);
    transpose_split_kernel<<<dim3(6, 32),  tb>>>(w_dkv_w,   1024, 192,  p_wdkvh, p_wdkvl);
    transpose_split_kernel<<<dim3(80, 4),  tb>>>(w_ukuv_w,  128, 2560,  p_wukuvh, p_wukuvl);
    transpose_half_kernel<<<dim3(32, 64),  tb>>>(w_o_w,     2048, 1024, p_wo16);

    // 1) cq = x @ w_dq + b (3-pass bf16)
    hgemm2_kernel<<<dim3(1, 32, 1), 256, GEMM_SMEM>>>(
        x, 1024, 0, p_wdqh, p_wdql, 1024, 0, w_dq_b, p_cq, 128, 0, 128, 1024, 1.f);
    // 2) rmsnorm
    rmsnorm128_kernel<<<MTOK, 128>>>(p_cq, q_norm_w);
    // 3) q = cq @ w_uq + b (3-pass bf16)
    hgemm2_kernel<<<dim3(8, 32, 1), 256, GEMM_SMEM>>>(
        p_cq, 128, 0, p_wuqh, p_wuql, 128, 0, w_uq_qr_b, p_q, 1024, 0, 1024, 128, 1.f);
    // 4) ckv_kr = x @ w_dkv + b (3-pass bf16)
    hgemm2_kernel<<<dim3(2, 32, 1), 256, GEMM_SMEM>>>(
        x, 1024, 0, p_wdkvh, p_wdkvl, 1024, 0, w_dkv_b, p_ckvkr, 192, 0, 192, 1024, 1.f);
    // 5) rmsnorm(ckv) + rope(k_rope)
    post_ckvkr_kernel<<<MTOK, 128>>>(p_ckvkr, kv_norm_w, pos, p_ckv, p_kr);
    // 6) kv = ckv @ w_ukuv + b (3-pass bf16)
    hgemm2_kernel<<<dim3(20, 32, 1), 256, GEMM_SMEM>>>(
        p_ckv, 128, 0, p_wukuvh, p_wukuvl, 128, 0, w_ukuv_b, p_kv, 2560, 0, 2560, 128, 1.f);
    // 7) build q/k/V^T fp16
    build_q_half_kernel<<<(NBATCH * Ss * 128) / 256, 256>>>(p_q, pos, p_q16);
    build_k_half_kernel<<<(NBATCH * Ss * 128) / 256, 256>>>(p_kv, p_kr, p_k16);
    build_vT_half_kernel<<<dim3(64, 8, NBATCH), tb>>>(p_kv, p_v16);
    // 8) scores = scale * Q @ K^T (1-pass fp16, fp16 out)
    hgemm16_kernel<1><<<dim3(16, 16, NBATCH), 256, PV_SMEM>>>(
        p_q16, 128, (long long)Ss * 128,
        p_k16, 128, (long long)Ss * 128,
        nullptr, nullptr, p_s16, Ss, (long long)Ss * Ss,
        Ss, 128, SCALE);
    // 9) softmax fp16 -> fp16
    softmax16_kernel<<<NBATCH * Ss, 256>>>(p_s16, p_p16);
    // 10) attn = P @ V (1-pass fp16, fp16 out permuted)
    hgemm16_kernel<2><<<dim3(2, 16, NBATCH), 256, PV_SMEM>>>(
        p_p16, Ss, (long long)Ss * Ss,
        p_v16, Ss, (long long)256 * Ss,
        nullptr, nullptr, p_attn16, 0, 0,
        256, Ss, 1.f);
    // 11) out = attn @ w_o + b (1-pass fp16, fp32 out)
    hgemm16_kernel<0><<<dim3(8, 32, 1), 256, PV_SMEM>>>(
        p_attn16, 2048, 0, p_wo16, 2048, 0,
        w_o_b, out, nullptr, 1024, 0,
        1024, 2048, 1.f);
}